// round 3
// baseline (speedup 1.0000x reference)
#include <cuda_runtime.h>
#include <cuda_bf16.h>
#include <cstdint>
#include <cstring>
#include <algorithm>

// ===================== Problem constants (static graph) =====================
#define VOCAB    512
#define T_LEN    64
#define D_MODEL  32
#define N_NODES  4000
#define N_LAYERS 5
#define N_BIAS   2
#define BATCH    512
#define N_IN     (T_LEN * D_MODEL)          // 2048
#define N_SRC0   (N_IN + N_BIAS)            // 2050 : first dst node id
#define N_DST    (N_NODES - N_SRC0)         // 1950 : hidden + vocab dst nodes
#define MAX_EDGES 262144                    // expected ~166.8k

// ===================== Device globals (no allocation allowed) ===============
__device__ int2  g_edges[MAX_EDGES];        // {src_node_id, weight_index}, dst-sorted
__device__ int   g_rowptr[N_DST + 2];       // CSR over local dst index
__device__ float g_vals[N_NODES][BATCH];    // transposed activation slab (8.2 MB)

// ===================== Host-side: numpy-exact MT19937 =======================
struct MT19937 {
    uint32_t mt[624];
    int idx;
    void seed(uint32_t s) {
        mt[0] = s;
        for (int i = 1; i < 624; i++)
            mt[i] = 1812433253u * (mt[i - 1] ^ (mt[i - 1] >> 30)) + (uint32_t)i;
        idx = 624;
    }
    inline uint32_t next() {
        if (idx >= 624) {
            for (int i = 0; i < 624; i++) {
                uint32_t y = (mt[i] & 0x80000000u) | (mt[(i + 1) % 624] & 0x7fffffffu);
                mt[i] = mt[(i + 397) % 624] ^ (y >> 1);
                if (y & 1u) mt[i] ^= 0x9908b0dfu;
            }
            idx = 0;
        }
        uint32_t y = mt[idx++];
        y ^= y >> 11;
        y ^= (y << 7)  & 0x9d2c5680u;
        y ^= (y << 15) & 0xefc60000u;
        y ^= y >> 18;
        return y;
    }
    inline double rdouble() {  // numpy legacy rk_double
        uint32_t a = next() >> 5, b = next() >> 6;
        return ((double)a * 67108864.0 + (double)b) / 9007199254740992.0;
    }
    inline uint64_t next64() {  // numpy mt19937_next64: hi then lo
        uint64_t hi = next();
        uint64_t lo = next();
        return (hi << 32) | lo;
    }
};

// ===================== Host graph build (exact numpy replica) ===============
struct LayerInfo { int node_base; int row_base; int size; };

static int2      h_edges[MAX_EDGES];   // static host arrays: read by GPU via ATS
static int       h_rowptr[N_DST + 2];
static LayerInfo h_layers[N_LAYERS + 1];
static int       h_nedges;

static void build_graph_host() {
    MT19937 mt;
    mt.seed(0u);

    int sizes[N_LAYERS + 1];
    {
        int nh = N_NODES - N_SRC0 - VOCAB;  // 1438
        for (int i = 0; i < N_LAYERS; i++)
            sizes[i] = nh / N_LAYERS + (i < nh % N_LAYERS ? 1 : 0);
        sizes[N_LAYERS] = VOCAB;
    }

    static int esrc[MAX_EDGES];
    static int edst[MAX_EDGES];

    int start = N_SRC0;
    int row_base = 0;
    int eidx = 0;

    for (int l = 0; l < N_LAYERS + 1; l++) {
        int size = sizes[l];
        int lbase = eidx;
        int colcnt[VOCAB];
        for (int v = 0; v < size; v++) colcnt[v] = 0;

        for (int u = 0; u < start; u++) {
            for (int v = 0; v < size; v++) {
                double x = mt.rdouble();
                if (x < 0.03) {
                    esrc[eidx] = u;
                    edst[eidx] = v;
                    colcnt[v]++;
                    eidx++;
                }
            }
        }

        // empty-column fix (probability ~1e-24; exact replica anyway)
        int emptyCols[VOCAB], nEmpty = 0;
        for (int v = 0; v < size; v++) if (colcnt[v] == 0) emptyCols[nEmpty++] = v;
        if (nEmpty) {
            uint64_t rng = (uint64_t)(start - 1);
            uint64_t mask = rng;
            mask |= mask >> 1; mask |= mask >> 2; mask |= mask >> 4;
            mask |= mask >> 8; mask |= mask >> 16; mask |= mask >> 32;
            for (int k = 0; k < nEmpty; k++) {
                uint64_t val;
                do { val = mt.next64() & mask; } while (val > rng);
                esrc[eidx] = (int)val;
                edst[eidx] = emptyCols[k];
                colcnt[emptyCols[k]]++;
                eidx++;
            }
            struct P { int s, d; };
            static P tmp[MAX_EDGES];
            int n = eidx - lbase;
            for (int i = 0; i < n; i++) tmp[i] = {esrc[lbase + i], edst[lbase + i]};
            std::sort(tmp, tmp + n, [](const P& a, const P& b) {
                return a.s != b.s ? a.s < b.s : a.d < b.d;
            });
            for (int i = 0; i < n; i++) { esrc[lbase + i] = tmp[i].s; edst[lbase + i] = tmp[i].d; }
        }

        // dst-sorted CSR; weight index = src-major position (== e)
        int colstart[VOCAB + 1];
        colstart[0] = lbase;
        for (int v = 0; v < size; v++) colstart[v + 1] = colstart[v] + colcnt[v];
        for (int v = 0; v < size; v++) h_rowptr[row_base + v] = colstart[v];
        int fill[VOCAB];
        for (int v = 0; v < size; v++) fill[v] = colstart[v];
        for (int e = lbase; e < eidx; e++) {
            int v = edst[e];
            h_edges[fill[v]].x = esrc[e];   // source node id
            h_edges[fill[v]].y = e;         // weight index
            fill[v]++;
        }

        h_layers[l].node_base = start;
        h_layers[l].row_base  = row_base;
        h_layers[l].size      = size;
        row_base += size;
        start    += size;
    }
    h_rowptr[N_DST] = eidx;
    h_nedges = eidx;
}

// ===================== Kernels ==============================================

// Pull graph metadata from HOST memory (Grace ATS / NVLink-C2C) into device
// globals. Pure kernel launch -> graph-capturable; ~1.35 MB @ ~200 GB/s ~ 7us.
__global__ void pull_graph_kernel(const int2* __restrict__ hostE,
                                  const int*  __restrict__ hostR,
                                  int nE) {
    int i = blockIdx.x * blockDim.x + threadIdx.x;
    int stride = gridDim.x * blockDim.x;
    for (int e = i; e < nE; e += stride)
        g_edges[e] = hostE[e];
    if (i <= N_DST)
        g_rowptr[i] = hostR[i];
}

// vals[node][b] for input + bias nodes
__global__ void embed_kernel(const int* __restrict__ ids,
                             const float* __restrict__ tok,
                             const float* __restrict__ pos) {
    int b    = blockIdx.x * 32 + threadIdx.x;
    int node = blockIdx.y * blockDim.y + threadIdx.y;
    if (node >= N_SRC0) return;
    float v;
    if (node < N_IN) {
        int t = node >> 5;          // node = t*D + d, D = 32
        v = tok[ids[b * T_LEN + t] * D_MODEL + (node & 31)] + pos[node];
    } else {
        v = 1.0f;
    }
    g_vals[node][b] = v;
}

// One warp-row = one dst node. Each thread accumulates 4 batch columns
// (b, b+128, b+256, b+384): per edge -> 1 broadcast meta + 1 broadcast weight
// + 4 coalesced 128B value loads (MLP=4 covers L2 latency).
__global__ void layer_kernel(const float* __restrict__ weights,
                             float* __restrict__ out,
                             int node_base, int row_base, int size, int is_last) {
    int dst = blockIdx.y * blockDim.y + threadIdx.y;
    if (dst >= size) return;
    int b  = blockIdx.x * 32 + threadIdx.x;     // b in [0,128): columns b+128*k
    int e0 = g_rowptr[row_base + dst];
    int e1 = g_rowptr[row_base + dst + 1];
    float a0 = 0.f, a1 = 0.f, a2 = 0.f, a3 = 0.f;
    for (int e = e0; e < e1; e++) {
        int2 m = g_edges[e];                    // uniform across warp (broadcast)
        float w = weights[m.y];
        const float* row = g_vals[m.x];
        a0 += w * row[b];
        a1 += w * row[b + 128];
        a2 += w * row[b + 256];
        a3 += w * row[b + 384];
    }
    if (is_last) {
        out[(b      ) * VOCAB + dst] = a0;      // logits, [B, V] row-major
        out[(b + 128) * VOCAB + dst] = a1;
        out[(b + 256) * VOCAB + dst] = a2;
        out[(b + 384) * VOCAB + dst] = a3;
    } else {
        float* row = g_vals[node_base + dst];
        row[b      ] = tanhf(a0);
        row[b + 128] = tanhf(a1);
        row[b + 256] = tanhf(a2);
        row[b + 384] = tanhf(a3);
    }
}

// ===================== Launch ===============================================
extern "C" void kernel_launch(void* const* d_in, const int* in_sizes, int n_in,
                              void* d_out, int out_size) {
    const int*   ids = (const int*)  d_in[0];
    const float* tok = (const float*)d_in[1];
    const float* pos = (const float*)d_in[2];
    const float* wts = (const float*)d_in[3];
    float*       out = (float*)d_out;

    // Host-side, deterministic, rebuilt identically on every call.
    build_graph_host();

    // GPU pulls the static host arrays via ATS (no memcpy API, no registration).
    pull_graph_kernel<<<256, 256>>>(h_edges, h_rowptr, h_nedges);

    dim3 eblk(32, 8);
    embed_kernel<<<dim3(BATCH / 32, (N_SRC0 + 7) / 8), eblk>>>(ids, tok, pos);

    dim3 blk(32, 8);
    for (int l = 0; l < N_LAYERS + 1; l++) {
        int sz = h_layers[l].size;
        layer_kernel<<<dim3(BATCH / 128, (sz + 7) / 8), blk>>>(
            wts, out, h_layers[l].node_base, h_layers[l].row_base, sz,
            l == N_LAYERS ? 1 : 0);
    }
}

// round 4
// speedup vs baseline: 1.9836x; 1.9836x over previous
#include <cuda_runtime.h>
#include <cuda_bf16.h>
#include <cstdint>
#include <cstring>
#include <algorithm>

// ===================== Problem constants (static graph) =====================
#define VOCAB    512
#define T_LEN    64
#define D_MODEL  32
#define N_NODES  4000
#define N_LAYERS 5
#define N_BIAS   2
#define BATCH    512
#define N_IN     (T_LEN * D_MODEL)          // 2048
#define N_SRC0   (N_IN + N_BIAS)            // 2050 : first dst node id
#define N_DST    (N_NODES - N_SRC0)         // 1950 : hidden + vocab dst nodes
#define MAX_EDGES 262144                    // expected ~166.8k

#define NSEG 4                               // edge segments per dst row
#define NDST 2                               // dst rows per block

// ===================== Device globals (no allocation allowed) ===============
__device__ float2 g_packed[MAX_EDGES];      // {weight, __int_as_float(src*BATCH)}
__device__ int    g_rowptr[N_DST + 2];      // CSR over local dst index
__device__ float  g_vals[N_NODES * BATCH];  // transposed activation slab (8.2 MB)

// ===================== Host-side: numpy-exact MT19937 =======================
struct MT19937 {
    uint32_t mt[624];
    int idx;
    void seed(uint32_t s) {
        mt[0] = s;
        for (int i = 1; i < 624; i++)
            mt[i] = 1812433253u * (mt[i - 1] ^ (mt[i - 1] >> 30)) + (uint32_t)i;
        idx = 624;
    }
    inline uint32_t next() {
        if (idx >= 624) {
            for (int i = 0; i < 624; i++) {
                uint32_t y = (mt[i] & 0x80000000u) | (mt[(i + 1) % 624] & 0x7fffffffu);
                mt[i] = mt[(i + 397) % 624] ^ (y >> 1);
                if (y & 1u) mt[i] ^= 0x9908b0dfu;
            }
            idx = 0;
        }
        uint32_t y = mt[idx++];
        y ^= y >> 11;
        y ^= (y << 7)  & 0x9d2c5680u;
        y ^= (y << 15) & 0xefc60000u;
        y ^= y >> 18;
        return y;
    }
    inline double rdouble() {  // numpy legacy rk_double
        uint32_t a = next() >> 5, b = next() >> 6;
        return ((double)a * 67108864.0 + (double)b) / 9007199254740992.0;
    }
    inline uint64_t next64() {  // numpy mt19937_next64: hi then lo
        uint64_t hi = next();
        uint64_t lo = next();
        return (hi << 32) | lo;
    }
};

// ===================== Host graph build (exact numpy replica) ===============
struct LayerInfo { int node_base; int row_base; int size; };

static uint32_t  h_emeta[MAX_EDGES];   // (widx << 12) | src  : GPU reads via ATS
static int       h_rowptr[N_DST + 2];
static LayerInfo h_layers[N_LAYERS + 1];
static int       h_nedges;

static void build_graph_host() {
    MT19937 mt;
    mt.seed(0u);

    int sizes[N_LAYERS + 1];
    {
        int nh = N_NODES - N_SRC0 - VOCAB;  // 1438
        for (int i = 0; i < N_LAYERS; i++)
            sizes[i] = nh / N_LAYERS + (i < nh % N_LAYERS ? 1 : 0);
        sizes[N_LAYERS] = VOCAB;
    }

    static int esrc[MAX_EDGES];
    static int edst[MAX_EDGES];

    int start = N_SRC0;
    int row_base = 0;
    int eidx = 0;

    for (int l = 0; l < N_LAYERS + 1; l++) {
        int size = sizes[l];
        int lbase = eidx;
        int colcnt[VOCAB];
        for (int v = 0; v < size; v++) colcnt[v] = 0;

        for (int u = 0; u < start; u++) {
            for (int v = 0; v < size; v++) {
                double x = mt.rdouble();
                if (x < 0.03) {
                    esrc[eidx] = u;
                    edst[eidx] = v;
                    colcnt[v]++;
                    eidx++;
                }
            }
        }

        // empty-column fix (probability ~1e-24; exact replica anyway)
        int emptyCols[VOCAB], nEmpty = 0;
        for (int v = 0; v < size; v++) if (colcnt[v] == 0) emptyCols[nEmpty++] = v;
        if (nEmpty) {
            uint64_t rng = (uint64_t)(start - 1);
            uint64_t mask = rng;
            mask |= mask >> 1; mask |= mask >> 2; mask |= mask >> 4;
            mask |= mask >> 8; mask |= mask >> 16; mask |= mask >> 32;
            for (int k = 0; k < nEmpty; k++) {
                uint64_t val;
                do { val = mt.next64() & mask; } while (val > rng);
                esrc[eidx] = (int)val;
                edst[eidx] = emptyCols[k];
                colcnt[emptyCols[k]]++;
                eidx++;
            }
            struct P { int s, d; };
            static P tmp[MAX_EDGES];
            int n = eidx - lbase;
            for (int i = 0; i < n; i++) tmp[i] = {esrc[lbase + i], edst[lbase + i]};
            std::sort(tmp, tmp + n, [](const P& a, const P& b) {
                return a.s != b.s ? a.s < b.s : a.d < b.d;
            });
            for (int i = 0; i < n; i++) { esrc[lbase + i] = tmp[i].s; edst[lbase + i] = tmp[i].d; }
        }

        // dst-sorted CSR; weight index = src-major position (== e)
        int colstart[VOCAB + 1];
        colstart[0] = lbase;
        for (int v = 0; v < size; v++) colstart[v + 1] = colstart[v] + colcnt[v];
        for (int v = 0; v < size; v++) h_rowptr[row_base + v] = colstart[v];
        int fill[VOCAB];
        for (int v = 0; v < size; v++) fill[v] = colstart[v];
        for (int e = lbase; e < eidx; e++) {
            int v = edst[e];
            h_emeta[fill[v]] = ((uint32_t)e << 12) | (uint32_t)esrc[e];
            fill[v]++;
        }

        h_layers[l].node_base = start;
        h_layers[l].row_base  = row_base;
        h_layers[l].size      = size;
        row_base += size;
        start    += size;
    }
    h_rowptr[N_DST] = eidx;
    h_nedges = eidx;
}

// ===================== Kernels ==============================================

// Pull compressed graph meta from HOST memory (Grace ATS / NVLink-C2C),
// gather runtime weights, and write packed edge records {w, src_offset}.
// Pure kernel launch -> graph-capturable; ~0.68 MB host traffic ~ 3.5us.
__global__ void pull_pack_kernel(const uint32_t* __restrict__ hostE,
                                 const int*      __restrict__ hostR,
                                 const float*    __restrict__ weights,
                                 int nE) {
    int i = blockIdx.x * blockDim.x + threadIdx.x;
    int stride = gridDim.x * blockDim.x;
    for (int e = i; e < nE; e += stride) {
        uint32_t v = hostE[e];
        int src  = (int)(v & 0xFFFu);
        int widx = (int)(v >> 12);
        g_packed[e] = make_float2(weights[widx], __int_as_float(src * BATCH));
    }
    for (int r = i; r <= N_DST; r += stride)
        g_rowptr[r] = hostR[r];
}

// vals[node][b] for input + bias nodes
__global__ void embed_kernel(const int* __restrict__ ids,
                             const float* __restrict__ tok,
                             const float* __restrict__ pos) {
    int b    = blockIdx.x * 32 + threadIdx.x;
    int node = blockIdx.y * blockDim.y + threadIdx.y;
    if (node >= N_SRC0) return;
    float v;
    if (node < N_IN) {
        int t = node >> 5;          // node = t*D + d, D = 32
        v = tok[ids[b * T_LEN + t] * D_MODEL + (node & 31)] + pos[node];
    } else {
        v = 1.0f;
    }
    g_vals[node * BATCH + b] = v;
}

// Block = 32 lanes x NSEG edge-segments x NDST dst rows.
// Each warp: one dst row, one quarter of its edge list, 128 batch columns
// (cols b, b+128, b+256, b+384 with b = blockIdx.x*32 + lane).
// Per edge: 1 broadcast float2 {w, srcoff} + 4 independent coalesced loads.
// Segments reduced through smem; seg-0 warps finalize (tanh / logit store).
__global__ void layer_kernel(float* __restrict__ out,
                             int node_base, int row_base, int size, int is_last) {
    __shared__ float red[NDST][NSEG][32][4];

    int lane = threadIdx.x;
    int seg  = threadIdx.y;
    int ld   = threadIdx.z;
    int dst  = blockIdx.y * NDST + ld;
    int b    = blockIdx.x * 32 + lane;

    float a0 = 0.f, a1 = 0.f, a2 = 0.f, a3 = 0.f;
    if (dst < size) {
        int e0  = g_rowptr[row_base + dst];
        int len = g_rowptr[row_base + dst + 1] - e0;
        int es  = e0 + (len * seg) / NSEG;
        int ee  = e0 + (len * (seg + 1)) / NSEG;
        for (int e = es; e < ee; e++) {
            float2 p = g_packed[e];             // uniform across warp (broadcast)
            const float* row = g_vals + __float_as_int(p.y);
            a0 = fmaf(p.x, row[b      ], a0);
            a1 = fmaf(p.x, row[b + 128], a1);
            a2 = fmaf(p.x, row[b + 256], a2);
            a3 = fmaf(p.x, row[b + 384], a3);
        }
    }
    red[ld][seg][lane][0] = a0;
    red[ld][seg][lane][1] = a1;
    red[ld][seg][lane][2] = a2;
    red[ld][seg][lane][3] = a3;
    __syncthreads();

    if (seg == 0 && dst < size) {
        float s0 = red[ld][0][lane][0] + red[ld][1][lane][0] +
                   red[ld][2][lane][0] + red[ld][3][lane][0];
        float s1 = red[ld][0][lane][1] + red[ld][1][lane][1] +
                   red[ld][2][lane][1] + red[ld][3][lane][1];
        float s2 = red[ld][0][lane][2] + red[ld][1][lane][2] +
                   red[ld][2][lane][2] + red[ld][3][lane][2];
        float s3 = red[ld][0][lane][3] + red[ld][1][lane][3] +
                   red[ld][2][lane][3] + red[ld][3][lane][3];
        if (is_last) {
            out[(b      ) * VOCAB + dst] = s0;  // logits, [B, V] row-major
            out[(b + 128) * VOCAB + dst] = s1;
            out[(b + 256) * VOCAB + dst] = s2;
            out[(b + 384) * VOCAB + dst] = s3;
        } else {
            float* row = g_vals + (node_base + dst) * BATCH;
            row[b      ] = tanhf(s0);
            row[b + 128] = tanhf(s1);
            row[b + 256] = tanhf(s2);
            row[b + 384] = tanhf(s3);
        }
    }
}

// ===================== Launch ===============================================
extern "C" void kernel_launch(void* const* d_in, const int* in_sizes, int n_in,
                              void* d_out, int out_size) {
    const int*   ids = (const int*)  d_in[0];
    const float* tok = (const float*)d_in[1];
    const float* pos = (const float*)d_in[2];
    const float* wts = (const float*)d_in[3];
    float*       out = (float*)d_out;

    // Host-side, deterministic, rebuilt identically on every call.
    build_graph_host();

    pull_pack_kernel<<<1024, 256>>>(h_emeta, h_rowptr, wts, h_nedges);

    dim3 eblk(32, 8);
    embed_kernel<<<dim3(BATCH / 32, (N_SRC0 + 7) / 8), eblk>>>(ids, tok, pos);

    dim3 blk(32, NSEG, NDST);
    for (int l = 0; l < N_LAYERS + 1; l++) {
        int sz = h_layers[l].size;
        layer_kernel<<<dim3(BATCH / 128, (sz + NDST - 1) / NDST), blk>>>(
            out, h_layers[l].node_base, h_layers[l].row_base, sz,
            l == N_LAYERS ? 1 : 0);
    }
}

// round 7
// speedup vs baseline: 2.0373x; 1.0271x over previous
#include <cuda_runtime.h>
#include <cuda_bf16.h>
#include <cstdint>
#include <cstring>
#include <algorithm>

// ===================== Problem constants (static graph) =====================
#define VOCAB    512
#define T_LEN    64
#define D_MODEL  32
#define N_NODES  4000
#define N_LAYERS 5
#define N_BIAS   2
#define BATCH    512
#define N_IN     (T_LEN * D_MODEL)          // 2048
#define N_SRC0   (N_IN + N_BIAS)            // 2050 : first dst node id
#define N_DST    (N_NODES - N_SRC0)         // 1950 : hidden + vocab dst nodes
#define MAX_EDGES 262144                    // expected ~166.8k

#define NSEG 8                               // edge segments per dst row
#define NDST 2                               // dst rows per block
#define TPB  (32 * NSEG * NDST)              // 512 threads, flat 1-D block

// ===================== Device globals (no allocation allowed) ===============
__device__ float2 g_packed[MAX_EDGES];                   // {weight, __int_as_float(src*BATCH)}
__device__ int    g_rowptr[N_DST + 2];                   // CSR over local dst index
__device__ __align__(128) float g_vals[N_NODES * BATCH]; // transposed activation slab (8.2 MB)

// ===================== Host-side: numpy-exact MT19937 =======================
struct MT19937 {
    uint32_t mt[624];
    int idx;
    void seed(uint32_t s) {
        mt[0] = s;
        for (int i = 1; i < 624; i++)
            mt[i] = 1812433253u * (mt[i - 1] ^ (mt[i - 1] >> 30)) + (uint32_t)i;
        idx = 624;
    }
    inline uint32_t next() {
        if (idx >= 624) {
            for (int i = 0; i < 624; i++) {
                uint32_t y = (mt[i] & 0x80000000u) | (mt[(i + 1) % 624] & 0x7fffffffu);
                mt[i] = mt[(i + 397) % 624] ^ (y >> 1);
                if (y & 1u) mt[i] ^= 0x9908b0dfu;
            }
            idx = 0;
        }
        uint32_t y = mt[idx++];
        y ^= y >> 11;
        y ^= (y << 7)  & 0x9d2c5680u;
        y ^= (y << 15) & 0xefc60000u;
        y ^= y >> 18;
        return y;
    }
    inline double rdouble() {  // numpy legacy rk_double
        uint32_t a = next() >> 5, b = next() >> 6;
        return ((double)a * 67108864.0 + (double)b) / 9007199254740992.0;
    }
    inline uint64_t next64() {  // numpy mt19937_next64: hi then lo
        uint64_t hi = next();
        uint64_t lo = next();
        return (hi << 32) | lo;
    }
};

// ===================== Host graph build (exact numpy replica) ===============
struct LayerInfo { int node_base; int row_base; int size; };

static uint32_t  h_emeta[MAX_EDGES];   // (widx << 12) | src  : GPU reads via ATS
static int       h_rowptr[N_DST + 2];
static LayerInfo h_layers[N_LAYERS + 1];
static int       h_nedges;

static void build_graph_host() {
    MT19937 mt;
    mt.seed(0u);

    int sizes[N_LAYERS + 1];
    {
        int nh = N_NODES - N_SRC0 - VOCAB;  // 1438
        for (int i = 0; i < N_LAYERS; i++)
            sizes[i] = nh / N_LAYERS + (i < nh % N_LAYERS ? 1 : 0);
        sizes[N_LAYERS] = VOCAB;
    }

    static int esrc[MAX_EDGES];
    static int edst[MAX_EDGES];

    int start = N_SRC0;
    int row_base = 0;
    int eidx = 0;

    for (int l = 0; l < N_LAYERS + 1; l++) {
        int size = sizes[l];
        int lbase = eidx;
        int colcnt[VOCAB];
        for (int v = 0; v < size; v++) colcnt[v] = 0;

        for (int u = 0; u < start; u++) {
            for (int v = 0; v < size; v++) {
                double x = mt.rdouble();
                if (x < 0.03) {
                    esrc[eidx] = u;
                    edst[eidx] = v;
                    colcnt[v]++;
                    eidx++;
                }
            }
        }

        // empty-column fix (probability ~1e-24; exact replica anyway)
        int emptyCols[VOCAB], nEmpty = 0;
        for (int v = 0; v < size; v++) if (colcnt[v] == 0) emptyCols[nEmpty++] = v;
        if (nEmpty) {
            uint64_t rng = (uint64_t)(start - 1);
            uint64_t mask = rng;
            mask |= mask >> 1; mask |= mask >> 2; mask |= mask >> 4;
            mask |= mask >> 8; mask |= mask >> 16; mask |= mask >> 32;
            for (int k = 0; k < nEmpty; k++) {
                uint64_t val;
                do { val = mt.next64() & mask; } while (val > rng);
                esrc[eidx] = (int)val;
                edst[eidx] = emptyCols[k];
                colcnt[emptyCols[k]]++;
                eidx++;
            }
            struct P { int s, d; };
            static P tmp[MAX_EDGES];
            int n = eidx - lbase;
            for (int i = 0; i < n; i++) tmp[i] = {esrc[lbase + i], edst[lbase + i]};
            std::sort(tmp, tmp + n, [](const P& a, const P& b) {
                return a.s != b.s ? a.s < b.s : a.d < b.d;
            });
            for (int i = 0; i < n; i++) { esrc[lbase + i] = tmp[i].s; edst[lbase + i] = tmp[i].d; }
        }

        // dst-sorted CSR; weight index = src-major position (== e)
        int colstart[VOCAB + 1];
        colstart[0] = lbase;
        for (int v = 0; v < size; v++) colstart[v + 1] = colstart[v] + colcnt[v];
        for (int v = 0; v < size; v++) h_rowptr[row_base + v] = colstart[v];
        int fill[VOCAB];
        for (int v = 0; v < size; v++) fill[v] = colstart[v];
        for (int e = lbase; e < eidx; e++) {
            int v = edst[e];
            h_emeta[fill[v]] = ((uint32_t)e << 12) | (uint32_t)esrc[e];
            fill[v]++;
        }

        h_layers[l].node_base = start;
        h_layers[l].row_base  = row_base;
        h_layers[l].size      = size;
        row_base += size;
        start    += size;
    }
    h_rowptr[N_DST] = eidx;
    h_nedges = eidx;
}

// ===================== Kernels ==============================================

// Pull compressed graph meta from HOST memory (Grace ATS / NVLink-C2C),
// gather runtime weights, and write packed edge records {w, src_offset}.
// Pure kernel launch -> graph-capturable; ~0.68 MB host traffic ~ 3.5us.
__global__ void pull_pack_kernel(const uint32_t* __restrict__ hostE,
                                 const int*      __restrict__ hostR,
                                 const float*    __restrict__ weights,
                                 int nE) {
    int i = blockIdx.x * blockDim.x + threadIdx.x;
    int stride = gridDim.x * blockDim.x;
    for (int e = i; e < nE; e += stride) {
        uint32_t v = hostE[e];
        int src  = (int)(v & 0xFFFu);
        int widx = (int)(v >> 12);
        g_packed[e] = make_float2(weights[widx], __int_as_float(src * BATCH));
    }
    for (int r = i; r <= N_DST; r += stride)
        g_rowptr[r] = hostR[r];
}

// vals[node][b] for input + bias nodes
__global__ void embed_kernel(const int* __restrict__ ids,
                             const float* __restrict__ tok,
                             const float* __restrict__ pos) {
    int b    = blockIdx.x * 32 + (threadIdx.x & 31);
    int node = blockIdx.y * 8 + (threadIdx.x >> 5);
    if (node >= N_SRC0) return;
    float v;
    if (node < N_IN) {
        int t = node >> 5;          // node = t*D + d, D = 32
        v = tok[ids[b * T_LEN + t] * D_MODEL + (node & 31)] + pos[node];
    } else {
        v = 1.0f;
    }
    g_vals[node * BATCH + b] = v;
}

// Flat 512-thread block = 32 lanes x NSEG edge-segments x NDST dst rows.
// Each warp: one dst row, 1/NSEG of its edge list, 128 consecutive batch
// columns (lane owns float4 at c = blockIdx.x*128 + lane*4).
// Per edge: 1 broadcast LDG.64 {w, srcoff} + 1 coalesced LDG.128 + 4 FMA.
// Segments reduced through smem; seg-0 warps finalize (tanh / logit store).
__global__ void __launch_bounds__(TPB, 2)
layer_kernel(float* __restrict__ out,
             int node_base, int row_base, int size, int is_last) {
    __shared__ float4 red[NDST][NSEG][32];

    int tid  = threadIdx.x;
    int lane = tid & 31;
    int seg  = (tid >> 5) & (NSEG - 1);
    int ld   = tid >> 8;                        // warp / NSEG
    int dst  = blockIdx.y * NDST + ld;
    int c    = blockIdx.x * 128 + lane * 4;     // 4 consecutive batch columns

    float4 a = make_float4(0.f, 0.f, 0.f, 0.f);
    if (dst < size) {
        int e0  = g_rowptr[row_base + dst];
        int len = g_rowptr[row_base + dst + 1] - e0;
        int es  = e0 + (len * seg) / NSEG;
        int ee  = e0 + (len * (seg + 1)) / NSEG;
        for (int e = es; e < ee; e++) {
            float2 p = g_packed[e];             // uniform across warp (broadcast)
            float4 v = *(const float4*)(g_vals + __float_as_int(p.y) + c);
            a.x = fmaf(p.x, v.x, a.x);
            a.y = fmaf(p.x, v.y, a.y);
            a.z = fmaf(p.x, v.z, a.z);
            a.w = fmaf(p.x, v.w, a.w);
        }
    }
    red[ld][seg][lane] = a;
    __syncthreads();

    if (seg == 0 && dst < size) {
        float4 s = red[ld][0][lane];
        #pragma unroll
        for (int k = 1; k < NSEG; k++) {
            float4 t = red[ld][k][lane];
            s.x += t.x; s.y += t.y; s.z += t.z; s.w += t.w;
        }
        if (is_last) {
            out[(c    ) * VOCAB + dst] = s.x;   // logits, [B, V] row-major
            out[(c + 1) * VOCAB + dst] = s.y;
            out[(c + 2) * VOCAB + dst] = s.z;
            out[(c + 3) * VOCAB + dst] = s.w;
        } else {
            float4 r;
            r.x = tanhf(s.x); r.y = tanhf(s.y);
            r.z = tanhf(s.z); r.w = tanhf(s.w);
            *(float4*)(g_vals + (node_base + dst) * BATCH + c) = r;
        }
    }
}

// ===================== Launch ===============================================
extern "C" void kernel_launch(void* const* d_in, const int* in_sizes, int n_in,
                              void* d_out, int out_size) {
    const int*   ids = (const int*)  d_in[0];
    const float* tok = (const float*)d_in[1];
    const float* pos = (const float*)d_in[2];
    const float* wts = (const float*)d_in[3];
    float*       out = (float*)d_out;

    // Host-side, deterministic, rebuilt identically on every call.
    build_graph_host();

    pull_pack_kernel<<<512, 256>>>(h_emeta, h_rowptr, wts, h_nedges);

    embed_kernel<<<dim3(BATCH / 32, (N_SRC0 + 7) / 8), 256>>>(ids, tok, pos);

    for (int l = 0; l < N_LAYERS + 1; l++) {
        int sz = h_layers[l].size;
        layer_kernel<<<dim3(BATCH / 128, (sz + NDST - 1) / NDST), TPB>>>(
            out, h_layers[l].node_base, h_layers[l].row_base, sz,
            l == N_LAYERS ? 1 : 0);
    }
}

// round 8
// speedup vs baseline: 2.2851x; 1.1216x over previous
#include <cuda_runtime.h>
#include <cuda_fp16.h>
#include <cstdint>
#include <cstring>
#include <algorithm>

// ===================== Problem constants (static graph) =====================
#define VOCAB    512
#define T_LEN    64
#define D_MODEL  32
#define N_NODES  4000
#define N_LAYERS 5
#define N_BIAS   2
#define BATCH    512
#define N_IN     (T_LEN * D_MODEL)          // 2048
#define N_SRC0   (N_IN + N_BIAS)            // 2050 : first dst node id
#define N_DST    (N_NODES - N_SRC0)         // 1950 : hidden + vocab dst nodes
#define MAX_EDGES 262144                    // expected ~166.8k

#define NSEG 8                               // edge segments per dst row
#define TPB  (32 * NSEG)                     // 256 threads, one dst row per block

// ===================== Device globals (no allocation allowed) ===============
__device__ float2 g_packed[MAX_EDGES];                    // {weight, __int_as_float(src*BATCH)}
__device__ int    g_rowptr[N_DST + 2];                    // CSR over local dst index
__device__ __align__(128) __half g_vals[N_NODES * BATCH]; // fp16 activation slab (4.1 MB)

// ===================== Host-side: numpy-exact MT19937 =======================
struct MT19937 {
    uint32_t mt[624];
    int idx;
    void seed(uint32_t s) {
        mt[0] = s;
        for (int i = 1; i < 624; i++)
            mt[i] = 1812433253u * (mt[i - 1] ^ (mt[i - 1] >> 30)) + (uint32_t)i;
        idx = 624;
    }
    inline uint32_t next() {
        if (idx >= 624) {
            for (int i = 0; i < 624; i++) {
                uint32_t y = (mt[i] & 0x80000000u) | (mt[(i + 1) % 624] & 0x7fffffffu);
                mt[i] = mt[(i + 397) % 624] ^ (y >> 1);
                if (y & 1u) mt[i] ^= 0x9908b0dfu;
            }
            idx = 0;
        }
        uint32_t y = mt[idx++];
        y ^= y >> 11;
        y ^= (y << 7)  & 0x9d2c5680u;
        y ^= (y << 15) & 0xefc60000u;
        y ^= y >> 18;
        return y;
    }
    inline double rdouble() {  // numpy legacy rk_double
        uint32_t a = next() >> 5, b = next() >> 6;
        return ((double)a * 67108864.0 + (double)b) / 9007199254740992.0;
    }
    inline uint64_t next64() {  // numpy mt19937_next64: hi then lo
        uint64_t hi = next();
        uint64_t lo = next();
        return (hi << 32) | lo;
    }
};

// ===================== Host graph build (exact numpy replica) ===============
struct LayerInfo { int node_base; int row_base; int size; };

static uint32_t  h_emeta[MAX_EDGES];   // (widx << 12) | src  : GPU reads via ATS
static int       h_rowptr[N_DST + 2];
static LayerInfo h_layers[N_LAYERS + 1];
static int       h_nedges;

static void build_graph_host() {
    MT19937 mt;
    mt.seed(0u);

    int sizes[N_LAYERS + 1];
    {
        int nh = N_NODES - N_SRC0 - VOCAB;  // 1438
        for (int i = 0; i < N_LAYERS; i++)
            sizes[i] = nh / N_LAYERS + (i < nh % N_LAYERS ? 1 : 0);
        sizes[N_LAYERS] = VOCAB;
    }

    static int esrc[MAX_EDGES];
    static int edst[MAX_EDGES];

    int start = N_SRC0;
    int row_base = 0;
    int eidx = 0;

    for (int l = 0; l < N_LAYERS + 1; l++) {
        int size = sizes[l];
        int lbase = eidx;
        int colcnt[VOCAB];
        for (int v = 0; v < size; v++) colcnt[v] = 0;

        for (int u = 0; u < start; u++) {
            for (int v = 0; v < size; v++) {
                double x = mt.rdouble();
                if (x < 0.03) {
                    esrc[eidx] = u;
                    edst[eidx] = v;
                    colcnt[v]++;
                    eidx++;
                }
            }
        }

        // empty-column fix (probability ~1e-24; exact replica anyway)
        int emptyCols[VOCAB], nEmpty = 0;
        for (int v = 0; v < size; v++) if (colcnt[v] == 0) emptyCols[nEmpty++] = v;
        if (nEmpty) {
            uint64_t rng = (uint64_t)(start - 1);
            uint64_t mask = rng;
            mask |= mask >> 1; mask |= mask >> 2; mask |= mask >> 4;
            mask |= mask >> 8; mask |= mask >> 16; mask |= mask >> 32;
            for (int k = 0; k < nEmpty; k++) {
                uint64_t val;
                do { val = mt.next64() & mask; } while (val > rng);
                esrc[eidx] = (int)val;
                edst[eidx] = emptyCols[k];
                colcnt[emptyCols[k]]++;
                eidx++;
            }
            struct P { int s, d; };
            static P tmp[MAX_EDGES];
            int n = eidx - lbase;
            for (int i = 0; i < n; i++) tmp[i] = {esrc[lbase + i], edst[lbase + i]};
            std::sort(tmp, tmp + n, [](const P& a, const P& b) {
                return a.s != b.s ? a.s < b.s : a.d < b.d;
            });
            for (int i = 0; i < n; i++) { esrc[lbase + i] = tmp[i].s; edst[lbase + i] = tmp[i].d; }
        }

        // dst-sorted CSR; weight index = src-major position (== e)
        int colstart[VOCAB + 1];
        colstart[0] = lbase;
        for (int v = 0; v < size; v++) colstart[v + 1] = colstart[v] + colcnt[v];
        for (int v = 0; v < size; v++) h_rowptr[row_base + v] = colstart[v];
        int fill[VOCAB];
        for (int v = 0; v < size; v++) fill[v] = colstart[v];
        for (int e = lbase; e < eidx; e++) {
            int v = edst[e];
            h_emeta[fill[v]] = ((uint32_t)e << 12) | (uint32_t)esrc[e];
            fill[v]++;
        }

        h_layers[l].node_base = start;
        h_layers[l].row_base  = row_base;
        h_layers[l].size      = size;
        row_base += size;
        start    += size;
    }
    h_rowptr[N_DST] = eidx;
    h_nedges = eidx;
}

// ===================== Kernels ==============================================

// Pull compressed graph meta from HOST memory (Grace ATS / NVLink-C2C),
// gather runtime weights, and write packed edge records {w, src_offset}.
// Pure kernel launch -> graph-capturable; ~0.68 MB host traffic ~ 3.5us.
__global__ void pull_pack_kernel(const uint32_t* __restrict__ hostE,
                                 const int*      __restrict__ hostR,
                                 const float*    __restrict__ weights,
                                 int nE) {
    int i = blockIdx.x * blockDim.x + threadIdx.x;
    int stride = gridDim.x * blockDim.x;
    for (int e = i; e < nE; e += stride) {
        uint32_t v = hostE[e];
        int src  = (int)(v & 0xFFFu);
        int widx = (int)(v >> 12);
        g_packed[e] = make_float2(weights[widx], __int_as_float(src * BATCH));
    }
    for (int r = i; r <= N_DST; r += stride)
        g_rowptr[r] = hostR[r];
}

// vals[node][b] for input + bias nodes (fp16)
__global__ void embed_kernel(const int* __restrict__ ids,
                             const float* __restrict__ tok,
                             const float* __restrict__ pos) {
    int b    = blockIdx.x * 32 + (threadIdx.x & 31);
    int node = blockIdx.y * 8 + (threadIdx.x >> 5);
    if (node >= N_SRC0) return;
    float v;
    if (node < N_IN) {
        int t = node >> 5;          // node = t*D + d, D = 32
        v = tok[ids[b * T_LEN + t] * D_MODEL + (node & 31)] + pos[node];
    } else {
        v = 1.0f;
    }
    g_vals[node * BATCH + b] = __float2half_rn(v);
}

// Flat 256-thread block = 32 lanes x NSEG edge-segments; one dst row/block.
// Each warp: 1/NSEG of the edge list, 128 consecutive batch columns
// (lane owns 4 cols as 2x half2 at c = blockIdx.x*128 + lane*4).
// Per edge: 1 broadcast LDG.64 {w, srcoff} + 1 coalesced LDG.64 of fp16 vals
// + 2 cvt + 4 FMA. Next edge record is prefetched (software pipeline).
// Segments reduced through smem; seg-0 warp finalizes (tanh / logit store).
__global__ void __launch_bounds__(TPB, 6)
layer_kernel(float* __restrict__ out,
             int node_base, int row_base, int size, int is_last) {
    __shared__ float4 red[NSEG][32];

    int tid  = threadIdx.x;
    int lane = tid & 31;
    int seg  = tid >> 5;
    int dst  = blockIdx.y;
    int c    = blockIdx.x * 128 + lane * 4;     // 4 consecutive batch columns

    float4 a = make_float4(0.f, 0.f, 0.f, 0.f);
    {
        int e0  = g_rowptr[row_base + dst];
        int len = g_rowptr[row_base + dst + 1] - e0;
        int es  = e0 + (len * seg) / NSEG;
        int ee  = e0 + (len * (seg + 1)) / NSEG;
        if (es < ee) {
            float2 p = g_packed[es];            // record for current edge
            for (int e = es + 1; e < ee; e++) {
                float2 pn = g_packed[e];        // prefetch next record
                uint2 raw = *(const uint2*)(g_vals + (__float_as_int(p.y) + c));
                float2 f01 = __half22float2(*reinterpret_cast<__half2*>(&raw.x));
                float2 f23 = __half22float2(*reinterpret_cast<__half2*>(&raw.y));
                a.x = fmaf(p.x, f01.x, a.x);
                a.y = fmaf(p.x, f01.y, a.y);
                a.z = fmaf(p.x, f23.x, a.z);
                a.w = fmaf(p.x, f23.y, a.w);
                p = pn;
            }
            uint2 raw = *(const uint2*)(g_vals + (__float_as_int(p.y) + c));
            float2 f01 = __half22float2(*reinterpret_cast<__half2*>(&raw.x));
            float2 f23 = __half22float2(*reinterpret_cast<__half2*>(&raw.y));
            a.x = fmaf(p.x, f01.x, a.x);
            a.y = fmaf(p.x, f01.y, a.y);
            a.z = fmaf(p.x, f23.x, a.z);
            a.w = fmaf(p.x, f23.y, a.w);
        }
    }
    red[seg][lane] = a;
    __syncthreads();

    if (seg == 0) {
        float4 s = red[0][lane];
        #pragma unroll
        for (int k = 1; k < NSEG; k++) {
            float4 t = red[k][lane];
            s.x += t.x; s.y += t.y; s.z += t.z; s.w += t.w;
        }
        if (is_last) {
            out[(c    ) * VOCAB + dst] = s.x;   // logits, [B, V] row-major, fp32
            out[(c + 1) * VOCAB + dst] = s.y;
            out[(c + 2) * VOCAB + dst] = s.z;
            out[(c + 3) * VOCAB + dst] = s.w;
        } else {
            __half2 h01 = __floats2half2_rn(tanhf(s.x), tanhf(s.y));
            __half2 h23 = __floats2half2_rn(tanhf(s.z), tanhf(s.w));
            uint2 raw;
            raw.x = *reinterpret_cast<uint32_t*>(&h01);
            raw.y = *reinterpret_cast<uint32_t*>(&h23);
            *(uint2*)(g_vals + ((node_base + dst) * BATCH + c)) = raw;
        }
    }
}

// ===================== Launch ===============================================
extern "C" void kernel_launch(void* const* d_in, const int* in_sizes, int n_in,
                              void* d_out, int out_size) {
    const int*   ids = (const int*)  d_in[0];
    const float* tok = (const float*)d_in[1];
    const float* pos = (const float*)d_in[2];
    const float* wts = (const float*)d_in[3];
    float*       out = (float*)d_out;

    // Host-side, deterministic, rebuilt identically on every call.
    build_graph_host();

    pull_pack_kernel<<<512, 256>>>(h_emeta, h_rowptr, wts, h_nedges);

    embed_kernel<<<dim3(BATCH / 32, (N_SRC0 + 7) / 8), 256>>>(ids, tok, pos);

    for (int l = 0; l < N_LAYERS + 1; l++) {
        int sz = h_layers[l].size;
        layer_kernel<<<dim3(BATCH / 128, sz), TPB>>>(
            out, h_layers[l].node_base, h_layers[l].row_base, sz,
            l == N_LAYERS ? 1 : 0);
    }
}